// round 13
// baseline (speedup 1.0000x reference)
#include <cuda_runtime.h>
#include <cuda_bf16.h>
#include <cuda_fp16.h>
#include <math.h>

// ---------------------------------------------------------------------------
// LSTM: S=512, B=64, I=256, H=512
// out = [h_seq (S,B,H) | h_final (B,H) | c_final (B,H)]  (fp32)
// xproj + recurrence both on mma.sync m16n8k16 (hi/lo fp16 splits ~ fp32).
// R13: recurrence MMA split into 4 independent accumulator chains.
// ---------------------------------------------------------------------------

#define S_LEN 512
#define BATCH 64
#define IN_DIM 256
#define HID 512
#define G4 2048              // 4*H
#define BH (BATCH*HID)       // 32768
#define BG (BATCH*G4)        // 131072
#define NCTA 128
#define BST 520              // rec B smem row stride (halves)

// xproj tiling: 64x128 CTA tile, warp tile 32x32, 2 CTAs/SM
#define XM 64
#define XN 128
#define XBK 32
#define XST 40               // xproj smem row stride (halves): 20 words/row
#define XA_BUF (XM*XST)      // 2560 halves per A buffer
#define XB_BUF (XN*XST)      // 5120 halves per B buffer
#define XP_SMEM ((4*XA_BUF + 2*XB_BUF) * 2)   // 40960 bytes

// -------------------- device scratch (static: no allocs allowed) ------------
__device__ float  g_xp[(size_t)S_LEN * BATCH * G4];  // x@Wx + bx + bh
__device__ __half g_WxT[(size_t)G4 * IN_DIM];        // WxT[n][k] fp16
__device__ float  g_WhT[(size_t)G4 * HID];           // WhT[col][k]
__device__ float  g_bias[G4];                        // bx + bh
__device__ __half g_hh[2][BH];                       // h hi fp16, ping-pong
__device__ __half g_hl[2][BH];                       // h lo fp16, ping-pong
__device__ unsigned int g_barc[4 * 32];              // per-bg counters

// fast activations
__device__ __forceinline__ float fast_exp(float x) {
    float e;
    asm("ex2.approx.f32 %0, %1;" : "=f"(e) : "f"(x * 1.4426950408889634f));
    return e;
}
__device__ __forceinline__ float fast_rcp(float x) {
    float r;
    asm("rcp.approx.f32 %0, %1;" : "=f"(r) : "f"(x));
    return r;
}
__device__ __forceinline__ float fast_sigmoid(float x) {
    return fast_rcp(1.f + fast_exp(-x));
}
__device__ __forceinline__ float fast_tanh(float x) {
    return 2.f * fast_rcp(1.f + fast_exp(-2.f * x)) - 1.f;
}

__device__ __forceinline__ void cpasync16(unsigned dst, const void* src) {
    asm volatile("cp.async.cg.shared.global [%0], [%1], 16;"
                 :: "r"(dst), "l"(src));
}

// mma.sync m16n8k16 row.col f32.f16.f16.f32 (accumulate in place)
__device__ __forceinline__ void hmma16816(float& d0, float& d1, float& d2, float& d3,
                                          unsigned a0, unsigned a1, unsigned a2, unsigned a3,
                                          unsigned b0, unsigned b1) {
    asm volatile(
        "mma.sync.aligned.m16n8k16.row.col.f32.f16.f16.f32 "
        "{%0,%1,%2,%3}, {%4,%5,%6,%7}, {%8,%9}, {%0,%1,%2,%3};"
        : "+f"(d0), "+f"(d1), "+f"(d2), "+f"(d3)
        : "r"(a0), "r"(a1), "r"(a2), "r"(a3), "r"(b0), "r"(b1));
}

// -------------------- merged prep kernel --------------------------------------
__global__ void prep_kernel(
    const float* __restrict__ Wxf, const float* __restrict__ Wxi,
    const float* __restrict__ Wxo, const float* __restrict__ Wxg,
    const float* __restrict__ Whf, const float* __restrict__ Whi,
    const float* __restrict__ Who, const float* __restrict__ Whg,
    const float* __restrict__ bxf, const float* __restrict__ bhf,
    const float* __restrict__ bxi, const float* __restrict__ bhi,
    const float* __restrict__ bxo, const float* __restrict__ bho,
    const float* __restrict__ bxg, const float* __restrict__ bhg)
{
    int idx = blockIdx.x * blockDim.x + threadIdx.x;

    if (idx < 4 * 32) g_barc[idx] = 0u;

    if (idx < G4) {
        int g = idx >> 9, jj = idx & 511;
        const float* bx = (g == 0) ? bxf : (g == 1) ? bxi : (g == 2) ? bxo : bxg;
        const float* bh = (g == 0) ? bhf : (g == 1) ? bhi : (g == 2) ? bho : bhg;
        g_bias[idx] = bx[jj] + bh[jj];
    }

    if (idx < G4 * IN_DIM) {         // g_WxT[n][k] = Wx_gate[k][unit] fp16
        int n = idx >> 8;
        int k = idx & 255;
        int g = n >> 9, unit = n & 511;
        const float* W = (g == 0) ? Wxf : (g == 1) ? Wxi : (g == 2) ? Wxo : Wxg;
        g_WxT[idx] = __float2half_rn(W[k * HID + unit]);
    }

    if (idx < G4 * HID) {
        int col = idx >> 9;
        int k   = idx & 511;
        int g   = col >> 9;
        int jj  = col & 511;
        const float* W = (g == 0) ? Whf : (g == 1) ? Whi : (g == 2) ? Who : Whg;
        g_WhT[idx] = W[k * HID + jj];   // WhT[col][k] = Wh[k][col]
    }
}

// -------------------- xproj via mma.sync (unchanged R12) -----------------------
__global__ __launch_bounds__(256, 2) void xproj_hmma(const float* __restrict__ x)
{
    extern __shared__ __half xs[];
    __half* a_hi = xs;                       // 2 x XA_BUF
    __half* a_lo = xs + 2 * XA_BUF;          // 2 x XA_BUF
    __half* bsm  = xs + 4 * XA_BUF;          // 2 x XB_BUF

    const int tid  = threadIdx.x;
    const int w    = tid >> 5;
    const int lane = tid & 31;
    const int g    = lane >> 2;
    const int tq   = lane & 3;
    const int mw   = w >> 2;                 // 0..1
    const int nw   = w & 3;                  // 0..3
    const int bm   = blockIdx.y * XM;
    const int bn   = blockIdx.x * XN;

    const int arow = tid >> 2;               // 0..63
    const int aq   = tid & 3;                // k-chunk of 8 floats
    const float* axp = x + (size_t)(bm + arow) * IN_DIM + aq * 8;

    const unsigned sb   = (unsigned)__cvta_generic_to_shared(xs);
    const unsigned bsmb = sb + (unsigned)(4 * XA_BUF) * 2u;

    float acc[2][4][4];
#pragma unroll
    for (int f = 0; f < 2; f++)
#pragma unroll
        for (int nf = 0; nf < 4; nf++)
#pragma unroll
            for (int q = 0; q < 4; q++) acc[f][nf][q] = 0.f;

#define CPB(p, ktg)                                                          \
    do {                                                                     \
        _Pragma("unroll")                                                    \
        for (int i = 0; i < 2; i++) {                                        \
            int idx = tid + (i << 8);                                        \
            int n   = idx >> 2;                                              \
            int ko  = (idx & 3) << 3;                                        \
            unsigned dst = bsmb + (unsigned)((p) * XB_BUF + n * XST + ko) * 2u; \
            cpasync16(dst, (const void*)(g_WxT + (size_t)(bn + n) * IN_DIM + (ktg) + ko)); \
        }                                                                    \
    } while (0)

#define STAGEA(p, v0, v1)                                                    \
    do {                                                                     \
        float ff[8] = {v0.x, v0.y, v0.z, v0.w, v1.x, v1.y, v1.z, v1.w};      \
        __align__(16) __half hh[8];                                          \
        __align__(16) __half hl[8];                                          \
        _Pragma("unroll")                                                    \
        for (int i = 0; i < 8; i++) {                                        \
            hh[i] = __float2half_rn(ff[i]);                                  \
            hl[i] = __float2half_rn(ff[i] - __half2float(hh[i]));            \
        }                                                                    \
        *(uint4*)(a_hi + (p) * XA_BUF + arow * XST + aq * 8) = *(uint4*)hh;  \
        *(uint4*)(a_lo + (p) * XA_BUF + arow * XST + aq * 8) = *(uint4*)hl;  \
    } while (0)

    // ---- prologue: tile 0 ----
    {
        CPB(0, 0);
        asm volatile("cp.async.commit_group;");
        float4 v0 = *(const float4*)(axp);
        float4 v1 = *(const float4*)(axp + 4);
        STAGEA(0, v0, v1);
        asm volatile("cp.async.wait_group 0;" ::: "memory");
    }
    __syncthreads();

#pragma unroll
    for (int kt = 0; kt < IN_DIM / XBK; kt++) {
        const int p = kt & 1;
        const bool has_next = (kt + 1) < (IN_DIM / XBK);

        float4 nv0, nv1;
        if (has_next) {
            CPB(p ^ 1, (kt + 1) * XBK);
            asm volatile("cp.async.commit_group;");
            nv0 = *(const float4*)(axp + (kt + 1) * XBK);
            nv1 = *(const float4*)(axp + (kt + 1) * XBK + 4);
        }

        const __half* ah_p = a_hi + p * XA_BUF;
        const __half* al_p = a_lo + p * XA_BUF;
        const __half* b_p  = bsm + p * XB_BUF;

#pragma unroll
        for (int ks = 0; ks < 2; ks++) {
            unsigned AH[2][4], AL[2][4], BB[4][2];
#pragma unroll
            for (int f = 0; f < 2; f++)
#pragma unroll
                for (int j = 0; j < 4; j++) {
                    int row = mw * 32 + f * 16 + g + ((j & 1) << 3);
                    int k   = ks * 16 + tq * 2 + ((j >> 1) << 3);
                    AH[f][j] = *(const unsigned*)(ah_p + row * XST + k);
                    AL[f][j] = *(const unsigned*)(al_p + row * XST + k);
                }
#pragma unroll
            for (int nf = 0; nf < 4; nf++) {
                int n = nw * 32 + nf * 8 + g;
                BB[nf][0] = *(const unsigned*)(b_p + n * XST + ks * 16 + tq * 2);
                BB[nf][1] = *(const unsigned*)(b_p + n * XST + ks * 16 + tq * 2 + 8);
            }
#pragma unroll
            for (int f = 0; f < 2; f++)
#pragma unroll
                for (int nf = 0; nf < 4; nf++) {
                    hmma16816(acc[f][nf][0], acc[f][nf][1], acc[f][nf][2], acc[f][nf][3],
                              AH[f][0], AH[f][1], AH[f][2], AH[f][3],
                              BB[nf][0], BB[nf][1]);
                    hmma16816(acc[f][nf][0], acc[f][nf][1], acc[f][nf][2], acc[f][nf][3],
                              AL[f][0], AL[f][1], AL[f][2], AL[f][3],
                              BB[nf][0], BB[nf][1]);
                }
        }

        if (has_next) {
            STAGEA(p ^ 1, nv0, nv1);
            asm volatile("cp.async.wait_group 0;" ::: "memory");
            __syncthreads();
        }
    }

    // ---- epilogue: bias add + store ----
#pragma unroll
    for (int nf = 0; nf < 4; nf++) {
        int col = bn + nw * 32 + nf * 8 + tq * 2;
        float b0 = g_bias[col];
        float b1 = g_bias[col + 1];
#pragma unroll
        for (int f = 0; f < 2; f++) {
            int r0 = bm + mw * 32 + f * 16 + g;
            float2 o0 = make_float2(acc[f][nf][0] + b0, acc[f][nf][1] + b1);
            float2 o1 = make_float2(acc[f][nf][2] + b0, acc[f][nf][3] + b1);
            *(float2*)&g_xp[(size_t)r0 * G4 + col]       = o0;
            *(float2*)&g_xp[(size_t)(r0 + 8) * G4 + col] = o1;
        }
    }
#undef CPB
#undef STAGEA
}

// -------------------- recurrence: mma.sync persistent --------------------------
// R13 change: Wh MMA uses 4 independent accumulator chains ({hi,lo} x {even,odd
// ks}) instead of one 64-deep RAW chain; combined with FADDs at the end.
__global__ __launch_bounds__(256, 1) void lstm_rec_kernel(float* __restrict__ out)
{
    __shared__ __align__(16) __half b_hi[16 * BST];
    __shared__ __align__(16) __half b_lo[16 * BST];
    __shared__ float rg[64 * 17];

    const int tid  = threadIdx.x;
    const int w    = tid >> 5;
    const int lane = tid & 31;
    const int g    = lane >> 2;
    const int tq   = lane & 3;
    const int mt   = w >> 1;
    const int nt   = w & 1;
    const int cta  = blockIdx.x;
    const int ug   = cta & 31;
    const int bg   = cta >> 5;

    unsigned ar[32][4];
#pragma unroll
    for (int ks = 0; ks < 32; ks++) {
#pragma unroll
        for (int j = 0; j < 4; j++) {
            int row  = mt * 16 + g + ((j & 1) << 3);
            int k    = ks * 16 + tq * 2 + ((j >> 1) << 3);
            int wcol = (row >> 4) * HID + (ug << 4) + (row & 15);
            float v0 = g_WhT[(size_t)wcol * HID + k];
            float v1 = g_WhT[(size_t)wcol * HID + k + 1];
            __half2 hv = __floats2half2_rn(v0, v1);
            ar[ks][j] = *(unsigned*)&hv;
        }
    }

    const __half* bhr = b_hi + (nt * 8 + g) * BST + tq * 2;
    const __half* blr = b_lo + (nt * 8 + g) * BST + tq * 2;

    const unsigned shi = (unsigned)__cvta_generic_to_shared(b_hi);
    const unsigned slo = (unsigned)__cvta_generic_to_shared(b_lo);

    const int ab = tid >> 4;
    const int au = tid & 15;
    const int gb = bg * 16 + ab;
    const int gj = (ug << 4) + au;

    unsigned int* barp = &g_barc[bg * 32];

    const size_t xof = (size_t)gb * G4 + gj;
    float c0 = g_xp[xof];
    float c1 = g_xp[xof + 512];
    float c2 = g_xp[xof + 1024];
    float c3 = g_xp[xof + 1536];

    float cval = 0.f;

    for (int t = 0; t < S_LEN; t++) {
        if (t > 0) {
            const int pp = (t - 1) & 1;
            const __half* s_hi = g_hh[pp] + (size_t)(bg * 16) * HID;
            const __half* s_lo = g_hl[pp] + (size_t)(bg * 16) * HID;
#pragma unroll
            for (int i = 0; i < 8; i++) {
                int idx  = tid + (i << 8);
                int buf  = idx >> 10;
                int rem  = idx & 1023;
                int lrow = rem >> 6;
                int ch   = rem & 63;
                const __half* src = (buf ? s_lo : s_hi) + lrow * HID + (ch << 3);
                unsigned dst = (buf ? slo : shi)
                               + (unsigned)(lrow * BST + (ch << 3)) * 2u;
                cpasync16(dst, (const void*)src);
            }
            asm volatile("cp.async.commit_group;");
            asm volatile("cp.async.wait_group 0;" ::: "memory");
            __syncthreads();
        }

        float n0 = 0.f, n1 = 0.f, n2 = 0.f, n3 = 0.f;
        if (t + 1 < S_LEN) {
            size_t nb = (size_t)(t + 1) * BG + xof;
            n0 = g_xp[nb]; n1 = g_xp[nb + 512];
            n2 = g_xp[nb + 1024]; n3 = g_xp[nb + 1536];
        }

        if (t > 0) {
            // 4 independent accumulator chains: {hi,lo} x {even,odd ks}
            float dA0 = 0.f, dA1 = 0.f, dA2 = 0.f, dA3 = 0.f;   // hi, even
            float dB0 = 0.f, dB1 = 0.f, dB2 = 0.f, dB3 = 0.f;   // hi, odd
            float dC0 = 0.f, dC1 = 0.f, dC2 = 0.f, dC3 = 0.f;   // lo, even
            float dD0 = 0.f, dD1 = 0.f, dD2 = 0.f, dD3 = 0.f;   // lo, odd
#pragma unroll
            for (int kp = 0; kp < 16; kp++) {
                const int ke = kp * 2;
                const int ko = kp * 2 + 1;
                unsigned b0he = *(const unsigned*)(bhr + ke * 16);
                unsigned b1he = *(const unsigned*)(bhr + ke * 16 + 8);
                unsigned b0ho = *(const unsigned*)(bhr + ko * 16);
                unsigned b1ho = *(const unsigned*)(bhr + ko * 16 + 8);
                unsigned b0le = *(const unsigned*)(blr + ke * 16);
                unsigned b1le = *(const unsigned*)(blr + ke * 16 + 8);
                unsigned b0lo = *(const unsigned*)(blr + ko * 16);
                unsigned b1lo = *(const unsigned*)(blr + ko * 16 + 8);
                hmma16816(dA0, dA1, dA2, dA3,
                          ar[ke][0], ar[ke][1], ar[ke][2], ar[ke][3], b0he, b1he);
                hmma16816(dB0, dB1, dB2, dB3,
                          ar[ko][0], ar[ko][1], ar[ko][2], ar[ko][3], b0ho, b1ho);
                hmma16816(dC0, dC1, dC2, dC3,
                          ar[ke][0], ar[ke][1], ar[ke][2], ar[ke][3], b0le, b1le);
                hmma16816(dD0, dD1, dD2, dD3,
                          ar[ko][0], ar[ko][1], ar[ko][2], ar[ko][3], b0lo, b1lo);
            }
            float d0 = (dA0 + dB0) + (dC0 + dD0);
            float d1 = (dA1 + dB1) + (dC1 + dD1);
            float d2 = (dA2 + dB2) + (dC2 + dD2);
            float d3 = (dA3 + dB3) + (dC3 + dD3);

            int row = mt * 16 + g;
            int col = nt * 8 + tq * 2;
            rg[row * 17 + col]           = d0;
            rg[row * 17 + col + 1]       = d1;
            rg[(row + 8) * 17 + col]     = d2;
            rg[(row + 8) * 17 + col + 1] = d3;
            __syncthreads();
        }

        float gf = c0, gi = c1, go = c2, gg = c3;
        if (t > 0) {
            gf += rg[(au +  0) * 17 + ab];
            gi += rg[(au + 16) * 17 + ab];
            go += rg[(au + 32) * 17 + ab];
            gg += rg[(au + 48) * 17 + ab];
        }
        c0 = n0; c1 = n1; c2 = n2; c3 = n3;

        float fg = fast_sigmoid(gf);
        float ig = fast_sigmoid(gi);
        float og = fast_sigmoid(go);
        float gt = fast_tanh(gg);
        cval = fg * cval + ig * gt;
        float hval = og * fast_tanh(cval);

        out[(size_t)t * BH + (size_t)gb * HID + gj] = hval;
        {
            const int p = t & 1;
            __half hi = __float2half_rn(hval);
            __half lo = __float2half_rn(hval - __half2float(hi));
            g_hh[p][(size_t)gb * HID + gj] = hi;
            g_hl[p][(size_t)gb * HID + gj] = lo;
        }

        if (t < S_LEN - 1) {
            __syncthreads();
            if (tid == 0) {
                asm volatile("red.release.gpu.global.add.u32 [%0], 1;"
                             :: "l"(barp) : "memory");
                unsigned target = (unsigned)(t + 1) * 32u;
                unsigned v;
                while (true) {
                    asm volatile("ld.acquire.gpu.global.u32 %0, [%1];"
                                 : "=r"(v) : "l"(barp) : "memory");
                    if (v >= target) break;
                    __nanosleep(20);
                }
            }
            __syncthreads();
        } else {
            out[(size_t)S_LEN * BH + (size_t)gb * HID + gj] = hval;        // h_f
            out[(size_t)S_LEN * BH + BH + (size_t)gb * HID + gj] = cval;   // c_f
        }
    }
}

// -------------------- launch ------------------------------------------------
extern "C" void kernel_launch(void* const* d_in, const int* in_sizes, int n_in,
                              void* d_out, int out_size)
{
    (void)in_sizes; (void)n_in; (void)out_size;
    const float* x   = (const float*)d_in[0];
    const float* Wxf = (const float*)d_in[1];
    const float* bxf = (const float*)d_in[2];
    const float* Whf = (const float*)d_in[3];
    const float* bhf = (const float*)d_in[4];
    const float* Wxi = (const float*)d_in[5];
    const float* bxi = (const float*)d_in[6];
    const float* Whi = (const float*)d_in[7];
    const float* bhi = (const float*)d_in[8];
    const float* Wxo = (const float*)d_in[9];
    const float* bxo = (const float*)d_in[10];
    const float* Who = (const float*)d_in[11];
    const float* bho = (const float*)d_in[12];
    const float* Wxg = (const float*)d_in[13];
    const float* bxg = (const float*)d_in[14];
    const float* Whg = (const float*)d_in[15];
    const float* bhg = (const float*)d_in[16];
    float* out = (float*)d_out;

    prep_kernel<<<(G4 * HID + 255) / 256, 256>>>(
        Wxf, Wxi, Wxo, Wxg, Whf, Whi, Who, Whg,
        bxf, bhf, bxi, bhi, bxo, bho, bxg, bhg);

    static bool attr_set = false;
    if (!attr_set) {
        cudaFuncSetAttribute(xproj_hmma,
                             cudaFuncAttributeMaxDynamicSharedMemorySize, XP_SMEM);
        attr_set = true;
    }
    dim3 gproj(G4 / XN, (S_LEN * BATCH) / XM);
    xproj_hmma<<<gproj, 256, XP_SMEM>>>(x);

    lstm_rec_kernel<<<NCTA, 256>>>(out);
}

// round 14
// speedup vs baseline: 1.1466x; 1.1466x over previous
#include <cuda_runtime.h>
#include <cuda_bf16.h>
#include <cuda_fp16.h>
#include <math.h>

// ---------------------------------------------------------------------------
// LSTM: S=512, B=64, I=256, H=512
// out = [h_seq (S,B,H) | h_final (B,H) | c_final (B,H)]  (fp32)
// xproj + recurrence both on mma.sync m16n8k16 (hi/lo fp16 splits ~ fp32).
// R14: rec partition 8bg x 16ug -> 16-arrival barriers, 16KB staging.
// ---------------------------------------------------------------------------

#define S_LEN 512
#define BATCH 64
#define IN_DIM 256
#define HID 512
#define G4 2048              // 4*H
#define BH (BATCH*HID)       // 32768
#define BG (BATCH*G4)        // 131072
#define NCTA 128
#define BST 520              // rec B smem row stride (halves)

// xproj tiling: 64x128 CTA tile, warp tile 32x32, 2 CTAs/SM
#define XM 64
#define XN 128
#define XBK 32
#define XST 40               // xproj smem row stride (halves): 20 words/row
#define XA_BUF (XM*XST)      // 2560 halves per A buffer
#define XB_BUF (XN*XST)      // 5120 halves per B buffer
#define XP_SMEM ((4*XA_BUF + 2*XB_BUF) * 2)   // 40960 bytes

// -------------------- device scratch (static: no allocs allowed) ------------
__device__ float  g_xp[(size_t)S_LEN * BATCH * G4];  // x@Wx + bx + bh
__device__ __half g_WxT[(size_t)G4 * IN_DIM];        // WxT[n][k] fp16
__device__ float  g_WhT[(size_t)G4 * HID];           // WhT[col][k]
__device__ float  g_bias[G4];                        // bx + bh
__device__ __half g_hh[2][BH];                       // h hi fp16, ping-pong
__device__ __half g_hl[2][BH];                       // h lo fp16, ping-pong
__device__ unsigned int g_barc[8 * 16];              // per-bg counters, 64B apart

// fast activations
__device__ __forceinline__ float fast_exp(float x) {
    float e;
    asm("ex2.approx.f32 %0, %1;" : "=f"(e) : "f"(x * 1.4426950408889634f));
    return e;
}
__device__ __forceinline__ float fast_rcp(float x) {
    float r;
    asm("rcp.approx.f32 %0, %1;" : "=f"(r) : "f"(x));
    return r;
}
__device__ __forceinline__ float fast_sigmoid(float x) {
    return fast_rcp(1.f + fast_exp(-x));
}
__device__ __forceinline__ float fast_tanh(float x) {
    return 2.f * fast_rcp(1.f + fast_exp(-2.f * x)) - 1.f;
}

__device__ __forceinline__ void cpasync16(unsigned dst, const void* src) {
    asm volatile("cp.async.cg.shared.global [%0], [%1], 16;"
                 :: "r"(dst), "l"(src));
}

// mma.sync m16n8k16 row.col f32.f16.f16.f32 (accumulate in place)
__device__ __forceinline__ void hmma16816(float& d0, float& d1, float& d2, float& d3,
                                          unsigned a0, unsigned a1, unsigned a2, unsigned a3,
                                          unsigned b0, unsigned b1) {
    asm volatile(
        "mma.sync.aligned.m16n8k16.row.col.f32.f16.f16.f32 "
        "{%0,%1,%2,%3}, {%4,%5,%6,%7}, {%8,%9}, {%0,%1,%2,%3};"
        : "+f"(d0), "+f"(d1), "+f"(d2), "+f"(d3)
        : "r"(a0), "r"(a1), "r"(a2), "r"(a3), "r"(b0), "r"(b1));
}

// -------------------- merged prep kernel --------------------------------------
__global__ void prep_kernel(
    const float* __restrict__ Wxf, const float* __restrict__ Wxi,
    const float* __restrict__ Wxo, const float* __restrict__ Wxg,
    const float* __restrict__ Whf, const float* __restrict__ Whi,
    const float* __restrict__ Who, const float* __restrict__ Whg,
    const float* __restrict__ bxf, const float* __restrict__ bhf,
    const float* __restrict__ bxi, const float* __restrict__ bhi,
    const float* __restrict__ bxo, const float* __restrict__ bho,
    const float* __restrict__ bxg, const float* __restrict__ bhg)
{
    int idx = blockIdx.x * blockDim.x + threadIdx.x;

    if (idx < 8 * 16) g_barc[idx] = 0u;

    if (idx < G4) {
        int g = idx >> 9, jj = idx & 511;
        const float* bx = (g == 0) ? bxf : (g == 1) ? bxi : (g == 2) ? bxo : bxg;
        const float* bh = (g == 0) ? bhf : (g == 1) ? bhi : (g == 2) ? bho : bhg;
        g_bias[idx] = bx[jj] + bh[jj];
    }

    if (idx < G4 * IN_DIM) {         // g_WxT[n][k] = Wx_gate[k][unit] fp16
        int n = idx >> 8;
        int k = idx & 255;
        int g = n >> 9, unit = n & 511;
        const float* W = (g == 0) ? Wxf : (g == 1) ? Wxi : (g == 2) ? Wxo : Wxg;
        g_WxT[idx] = __float2half_rn(W[k * HID + unit]);
    }

    if (idx < G4 * HID) {
        int col = idx >> 9;
        int k   = idx & 511;
        int g   = col >> 9;
        int jj  = col & 511;
        const float* W = (g == 0) ? Whf : (g == 1) ? Whi : (g == 2) ? Who : Whg;
        g_WhT[idx] = W[k * HID + jj];   // WhT[col][k] = Wh[k][col]
    }
}

// -------------------- xproj via mma.sync (unchanged R12) -----------------------
__global__ __launch_bounds__(256, 2) void xproj_hmma(const float* __restrict__ x)
{
    extern __shared__ __half xs[];
    __half* a_hi = xs;                       // 2 x XA_BUF
    __half* a_lo = xs + 2 * XA_BUF;          // 2 x XA_BUF
    __half* bsm  = xs + 4 * XA_BUF;          // 2 x XB_BUF

    const int tid  = threadIdx.x;
    const int w    = tid >> 5;
    const int lane = tid & 31;
    const int g    = lane >> 2;
    const int tq   = lane & 3;
    const int mw   = w >> 2;                 // 0..1
    const int nw   = w & 3;                  // 0..3
    const int bm   = blockIdx.y * XM;
    const int bn   = blockIdx.x * XN;

    const int arow = tid >> 2;               // 0..63
    const int aq   = tid & 3;                // k-chunk of 8 floats
    const float* axp = x + (size_t)(bm + arow) * IN_DIM + aq * 8;

    const unsigned sb   = (unsigned)__cvta_generic_to_shared(xs);
    const unsigned bsmb = sb + (unsigned)(4 * XA_BUF) * 2u;

    float acc[2][4][4];
#pragma unroll
    for (int f = 0; f < 2; f++)
#pragma unroll
        for (int nf = 0; nf < 4; nf++)
#pragma unroll
            for (int q = 0; q < 4; q++) acc[f][nf][q] = 0.f;

#define CPB(p, ktg)                                                          \
    do {                                                                     \
        _Pragma("unroll")                                                    \
        for (int i = 0; i < 2; i++) {                                        \
            int idx = tid + (i << 8);                                        \
            int n   = idx >> 2;                                              \
            int ko  = (idx & 3) << 3;                                        \
            unsigned dst = bsmb + (unsigned)((p) * XB_BUF + n * XST + ko) * 2u; \
            cpasync16(dst, (const void*)(g_WxT + (size_t)(bn + n) * IN_DIM + (ktg) + ko)); \
        }                                                                    \
    } while (0)

#define STAGEA(p, v0, v1)                                                    \
    do {                                                                     \
        float ff[8] = {v0.x, v0.y, v0.z, v0.w, v1.x, v1.y, v1.z, v1.w};      \
        __align__(16) __half hh[8];                                          \
        __align__(16) __half hl[8];                                          \
        _Pragma("unroll")                                                    \
        for (int i = 0; i < 8; i++) {                                        \
            hh[i] = __float2half_rn(ff[i]);                                  \
            hl[i] = __float2half_rn(ff[i] - __half2float(hh[i]));            \
        }                                                                    \
        *(uint4*)(a_hi + (p) * XA_BUF + arow * XST + aq * 8) = *(uint4*)hh;  \
        *(uint4*)(a_lo + (p) * XA_BUF + arow * XST + aq * 8) = *(uint4*)hl;  \
    } while (0)

    // ---- prologue: tile 0 ----
    {
        CPB(0, 0);
        asm volatile("cp.async.commit_group;");
        float4 v0 = *(const float4*)(axp);
        float4 v1 = *(const float4*)(axp + 4);
        STAGEA(0, v0, v1);
        asm volatile("cp.async.wait_group 0;" ::: "memory");
    }
    __syncthreads();

#pragma unroll
    for (int kt = 0; kt < IN_DIM / XBK; kt++) {
        const int p = kt & 1;
        const bool has_next = (kt + 1) < (IN_DIM / XBK);

        float4 nv0, nv1;
        if (has_next) {
            CPB(p ^ 1, (kt + 1) * XBK);
            asm volatile("cp.async.commit_group;");
            nv0 = *(const float4*)(axp + (kt + 1) * XBK);
            nv1 = *(const float4*)(axp + (kt + 1) * XBK + 4);
        }

        const __half* ah_p = a_hi + p * XA_BUF;
        const __half* al_p = a_lo + p * XA_BUF;
        const __half* b_p  = bsm + p * XB_BUF;

#pragma unroll
        for (int ks = 0; ks < 2; ks++) {
            unsigned AH[2][4], AL[2][4], BB[4][2];
#pragma unroll
            for (int f = 0; f < 2; f++)
#pragma unroll
                for (int j = 0; j < 4; j++) {
                    int row = mw * 32 + f * 16 + g + ((j & 1) << 3);
                    int k   = ks * 16 + tq * 2 + ((j >> 1) << 3);
                    AH[f][j] = *(const unsigned*)(ah_p + row * XST + k);
                    AL[f][j] = *(const unsigned*)(al_p + row * XST + k);
                }
#pragma unroll
            for (int nf = 0; nf < 4; nf++) {
                int n = nw * 32 + nf * 8 + g;
                BB[nf][0] = *(const unsigned*)(b_p + n * XST + ks * 16 + tq * 2);
                BB[nf][1] = *(const unsigned*)(b_p + n * XST + ks * 16 + tq * 2 + 8);
            }
#pragma unroll
            for (int f = 0; f < 2; f++)
#pragma unroll
                for (int nf = 0; nf < 4; nf++) {
                    hmma16816(acc[f][nf][0], acc[f][nf][1], acc[f][nf][2], acc[f][nf][3],
                              AH[f][0], AH[f][1], AH[f][2], AH[f][3],
                              BB[nf][0], BB[nf][1]);
                    hmma16816(acc[f][nf][0], acc[f][nf][1], acc[f][nf][2], acc[f][nf][3],
                              AL[f][0], AL[f][1], AL[f][2], AL[f][3],
                              BB[nf][0], BB[nf][1]);
                }
        }

        if (has_next) {
            STAGEA(p ^ 1, nv0, nv1);
            asm volatile("cp.async.wait_group 0;" ::: "memory");
            __syncthreads();
        }
    }

    // ---- epilogue: bias add + store ----
#pragma unroll
    for (int nf = 0; nf < 4; nf++) {
        int col = bn + nw * 32 + nf * 8 + tq * 2;
        float b0 = g_bias[col];
        float b1 = g_bias[col + 1];
#pragma unroll
        for (int f = 0; f < 2; f++) {
            int r0 = bm + mw * 32 + f * 16 + g;
            float2 o0 = make_float2(acc[f][nf][0] + b0, acc[f][nf][1] + b1);
            float2 o1 = make_float2(acc[f][nf][2] + b0, acc[f][nf][3] + b1);
            *(float2*)&g_xp[(size_t)r0 * G4 + col]       = o0;
            *(float2*)&g_xp[(size_t)(r0 + 8) * G4 + col] = o1;
        }
    }
#undef CPB
#undef STAGEA
}

// -------------------- recurrence: mma.sync persistent --------------------------
// R14: 128 CTAs = 8 bg (8 batches) x 16 ug (32 units). 256 threads = 8 warps.
// D[128 gate-rows, 8 batches] = Wh_slice[128 x 512] * h[8 x 512]^T.
// Warp w = m-tile (rows w*16..+15); all warps share the 8 batches (n=8).
// Gate-row r = gate*32 + unit (gate=r>>5, unit=r&31).
// Barrier: per-bg counter, 16 arrivals. Staging: 8 batches hi+lo = 16KB.
__global__ __launch_bounds__(256, 1) void lstm_rec_kernel(float* __restrict__ out)
{
    __shared__ __align__(16) __half b_hi[8 * BST];
    __shared__ __align__(16) __half b_lo[8 * BST];
    __shared__ float rg[128 * 9];

    const int tid  = threadIdx.x;
    const int w    = tid >> 5;
    const int lane = tid & 31;
    const int g    = lane >> 2;
    const int tq   = lane & 3;
    const int mt   = w;                 // 0..7 (rows mt*16..+15)
    const int cta  = blockIdx.x;
    const int ug   = cta & 15;          // units [ug*32, +32)
    const int bg   = cta >> 4;          // batches [bg*8, +8)

    // ---- Wh A-fragments (registers, once) ----
    unsigned ar[32][4];
#pragma unroll
    for (int ks = 0; ks < 32; ks++) {
#pragma unroll
        for (int j = 0; j < 4; j++) {
            int row  = mt * 16 + g + ((j & 1) << 3);     // 0..127
            int k    = ks * 16 + tq * 2 + ((j >> 1) << 3);
            int wcol = (row >> 5) * HID + (ug << 5) + (row & 31);
            float v0 = g_WhT[(size_t)wcol * HID + k];
            float v1 = g_WhT[(size_t)wcol * HID + k + 1];
            __half2 hv = __floats2half2_rn(v0, v1);
            ar[ks][j] = *(unsigned*)&hv;
        }
    }

    // B frag pointers: n-row = g (0..7)
    const __half* bhr = b_hi + g * BST + tq * 2;
    const __half* blr = b_lo + g * BST + tq * 2;

    const unsigned shi = (unsigned)__cvta_generic_to_shared(b_hi);
    const unsigned slo = (unsigned)__cvta_generic_to_shared(b_lo);

    // ---- activation mapping: (ab 0..7, au 0..31) ----
    const int ab = tid >> 5;
    const int au = tid & 31;
    const int gb = bg * 8 + ab;
    const int gj = (ug << 5) + au;

    unsigned int* barp = &g_barc[bg * 16];

    const size_t xof = (size_t)gb * G4 + gj;
    float c0 = g_xp[xof];
    float c1 = g_xp[xof + 512];
    float c2 = g_xp[xof + 1024];
    float c3 = g_xp[xof + 1536];

    float cval = 0.f;

    for (int t = 0; t < S_LEN; t++) {
        if (t > 0) {
            // ---- stage h(t-1) hi/lo: 8 rows x 512 halves each = 16KB ----
            const int pp = (t - 1) & 1;
            const __half* s_hi = g_hh[pp] + (size_t)(bg * 8) * HID;
            const __half* s_lo = g_hl[pp] + (size_t)(bg * 8) * HID;
#pragma unroll
            for (int i = 0; i < 4; i++) {          // 1024 16B-chunks / 256 thr
                int idx  = tid + (i << 8);
                int buf  = idx >> 9;               // 0: hi, 1: lo
                int rem  = idx & 511;
                int lrow = rem >> 6;
                int ch   = rem & 63;
                const __half* src = (buf ? s_lo : s_hi) + lrow * HID + (ch << 3);
                unsigned dst = (buf ? slo : shi)
                               + (unsigned)(lrow * BST + (ch << 3)) * 2u;
                cpasync16(dst, (const void*)src);
            }
            asm volatile("cp.async.commit_group;");
            asm volatile("cp.async.wait_group 0;" ::: "memory");
            __syncthreads();
        }

        // prefetch xp(t+1)
        float n0 = 0.f, n1 = 0.f, n2 = 0.f, n3 = 0.f;
        if (t + 1 < S_LEN) {
            size_t nb = (size_t)(t + 1) * BG + xof;
            n0 = g_xp[nb]; n1 = g_xp[nb + 512];
            n2 = g_xp[nb + 1024]; n3 = g_xp[nb + 1536];
        }

        if (t > 0) {
            float d0 = 0.f, d1 = 0.f, d2 = 0.f, d3 = 0.f;
#pragma unroll
            for (int ks = 0; ks < 32; ks++) {
                unsigned b0h = *(const unsigned*)(bhr + ks * 16);
                unsigned b1h = *(const unsigned*)(bhr + ks * 16 + 8);
                unsigned b0l = *(const unsigned*)(blr + ks * 16);
                unsigned b1l = *(const unsigned*)(blr + ks * 16 + 8);
                hmma16816(d0, d1, d2, d3,
                          ar[ks][0], ar[ks][1], ar[ks][2], ar[ks][3], b0h, b1h);
                hmma16816(d0, d1, d2, d3,
                          ar[ks][0], ar[ks][1], ar[ks][2], ar[ks][3], b0l, b1l);
            }
            // D frag -> rg: lane (g,tq) owns (row, col 2tq),(+1); rows +8 in d2/d3
            int row = mt * 16 + g;
            int col = tq * 2;
            rg[row * 9 + col]           = d0;
            rg[row * 9 + col + 1]       = d1;
            rg[(row + 8) * 9 + col]     = d2;
            rg[(row + 8) * 9 + col + 1] = d3;
            __syncthreads();
        }

        // ---- activation: thread (ab, au) ----
        float gf = c0, gi = c1, go = c2, gg = c3;
        if (t > 0) {
            gf += rg[(au +  0) * 9 + ab];
            gi += rg[(au + 32) * 9 + ab];
            go += rg[(au + 64) * 9 + ab];
            gg += rg[(au + 96) * 9 + ab];
        }
        c0 = n0; c1 = n1; c2 = n2; c3 = n3;

        float fg = fast_sigmoid(gf);
        float ig = fast_sigmoid(gi);
        float og = fast_sigmoid(go);
        float gt = fast_tanh(gg);
        cval = fg * cval + ig * gt;
        float hval = og * fast_tanh(cval);

        out[(size_t)t * BH + (size_t)gb * HID + gj] = hval;
        {
            const int p = t & 1;
            __half hi = __float2half_rn(hval);
            __half lo = __float2half_rn(hval - __half2float(hi));
            g_hh[p][(size_t)gb * HID + gj] = hi;
            g_hl[p][(size_t)gb * HID + gj] = lo;
        }

        if (t < S_LEN - 1) {
            // ---- per-bg barrier: 16 arrivals ----
            __syncthreads();
            if (tid == 0) {
                asm volatile("red.release.gpu.global.add.u32 [%0], 1;"
                             :: "l"(barp) : "memory");
                unsigned target = (unsigned)(t + 1) * 16u;
                unsigned v;
                while (true) {
                    asm volatile("ld.acquire.gpu.global.u32 %0, [%1];"
                                 : "=r"(v) : "l"(barp) : "memory");
                    if (v >= target) break;
                    __nanosleep(20);
                }
            }
            __syncthreads();
        } else {
            out[(size_t)S_LEN * BH + (size_t)gb * HID + gj] = hval;        // h_f
            out[(size_t)S_LEN * BH + BH + (size_t)gb * HID + gj] = cval;   // c_f
        }
    }
}

// -------------------- launch ------------------------------------------------
extern "C" void kernel_launch(void* const* d_in, const int* in_sizes, int n_in,
                              void* d_out, int out_size)
{
    (void)in_sizes; (void)n_in; (void)out_size;
    const float* x   = (const float*)d_in[0];
    const float* Wxf = (const float*)d_in[1];
    const float* bxf = (const float*)d_in[2];
    const float* Whf = (const float*)d_in[3];
    const float* bhf = (const float*)d_in[4];
    const float* Wxi = (const float*)d_in[5];
    const float* bxi = (const float*)d_in[6];
    const float* Whi = (const float*)d_in[7];
    const float* bhi = (const float*)d_in[8];
    const float* Wxo = (const float*)d_in[9];
    const float* bxo = (const float*)d_in[10];
    const float* Who = (const float*)d_in[11];
    const float* bho = (const float*)d_in[12];
    const float* Wxg = (const float*)d_in[13];
    const float* bxg = (const float*)d_in[14];
    const float* Whg = (const float*)d_in[15];
    const float* bhg = (const float*)d_in[16];
    float* out = (float*)d_out;

    prep_kernel<<<(G4 * HID + 255) / 256, 256>>>(
        Wxf, Wxi, Wxo, Wxg, Whf, Whi, Who, Whg,
        bxf, bhf, bxi, bhi, bxo, bho, bxg, bhg);

    static bool attr_set = false;
    if (!attr_set) {
        cudaFuncSetAttribute(xproj_hmma,
                             cudaFuncAttributeMaxDynamicSharedMemorySize, XP_SMEM);
        attr_set = true;
    }
    dim3 gproj(G4 / XN, (S_LEN * BATCH) / XM);
    xproj_hmma<<<gproj, 256, XP_SMEM>>>(x);

    lstm_rec_kernel<<<NCTA, 256>>>(out);
}